// round 5
// baseline (speedup 1.0000x reference)
#include <cuda_runtime.h>
#include <cstdint>

#define N_NODES 40000
#define N_EDGES 640000
#define D_IN    512
#define D_OUT   128

// ---------------------------------------------------------------------------
// __device__ scratch (allocation-free rule)
// ---------------------------------------------------------------------------
__device__ __align__(16) float g_seq[(size_t)N_NODES * D_OUT];  // 20.5 MB
__device__ int  g_counts[N_NODES + 1];
__device__ int  g_row_start[N_NODES + 1];
__device__ int  g_cursor[N_NODES + 1];
__device__ __align__(8) int2 g_sorted_cv[N_EDGES];  // {col, float_bits(val)}

// ---------------------------------------------------------------------------
// tf32 helpers
// ---------------------------------------------------------------------------
__device__ __forceinline__ uint32_t f2tf32(float f) {
    uint32_t u;
    asm("cvt.rna.tf32.f32 %0, %1;" : "=r"(u) : "f"(f));
    return u;
}

__device__ __forceinline__ void mma_tf32(float* c, const uint32_t* a,
                                         uint32_t b0, uint32_t b1) {
    asm volatile(
        "mma.sync.aligned.m16n8k8.row.col.f32.tf32.tf32.f32 "
        "{%0,%1,%2,%3}, {%4,%5,%6,%7}, {%8,%9}, {%0,%1,%2,%3};"
        : "+f"(c[0]), "+f"(c[1]), "+f"(c[2]), "+f"(c[3])
        : "r"(a[0]), "r"(a[1]), "r"(a[2]), "r"(a[3]), "r"(b0), "r"(b1));
}

// ---------------------------------------------------------------------------
// GEMM: seq[n][o] = sum_k x[n][k] * w[o][k]   (tf32 tensor cores)
// 128x128 block tile, BK=32, 256 threads = 8 warps (4x2), warp tile 32x64.
// ---------------------------------------------------------------------------
#define BK 32
#define LDS_PAD 36   // 36*4 = 144 bytes per row, 144 % 16 == 0

__global__ __launch_bounds__(256, 1) void gcn_gemm_tf32_kernel(
    const float* __restrict__ x, const float* __restrict__ w)
{
    __shared__ uint32_t As[128 * LDS_PAD];   // [m][k] tf32
    __shared__ uint32_t Bs[128 * LDS_PAD];   // [n][k] tf32

    const int tid    = threadIdx.x;
    const int lane   = tid & 31;
    const int wid    = tid >> 5;
    const int warp_m = wid & 3;
    const int warp_n = wid >> 2;
    const int m0     = blockIdx.x * 128;

    const int q    = tid & 7;
    const int mrow = tid >> 3;

    float acc[2][8][4];
#pragma unroll
    for (int mt = 0; mt < 2; mt++)
#pragma unroll
        for (int nt = 0; nt < 8; nt++)
#pragma unroll
            for (int j = 0; j < 4; j++) acc[mt][nt][j] = 0.f;

    float4 xv[4], wv[4];

#pragma unroll
    for (int r = 0; r < 4; r++) {
        int m  = mrow + r * 32;
        int gm = m0 + m;
        xv[r] = (gm < N_NODES)
            ? *reinterpret_cast<const float4*>(x + (size_t)gm * D_IN + q * 4)
            : make_float4(0.f, 0.f, 0.f, 0.f);
        wv[r] = *reinterpret_cast<const float4*>(w + (size_t)m * D_IN + q * 4);
    }

#pragma unroll 1
    for (int kt = 0; kt < D_IN / BK; kt++) {
#pragma unroll
        for (int r = 0; r < 4; r++) {
            int m    = mrow + r * 32;
            int base = m * LDS_PAD + q * 4;
            uint4 ta = make_uint4(f2tf32(xv[r].x), f2tf32(xv[r].y),
                                  f2tf32(xv[r].z), f2tf32(xv[r].w));
            uint4 tb = make_uint4(f2tf32(wv[r].x), f2tf32(wv[r].y),
                                  f2tf32(wv[r].z), f2tf32(wv[r].w));
            *reinterpret_cast<uint4*>(&As[base]) = ta;
            *reinterpret_cast<uint4*>(&Bs[base]) = tb;
        }
        __syncthreads();

        const bool more = (kt + 1) < (D_IN / BK);
        float4 xn[4], wn[4];
        if (more) {
            int k0 = (kt + 1) * BK;
#pragma unroll
            for (int r = 0; r < 4; r++) {
                int m  = mrow + r * 32;
                int gm = m0 + m;
                xn[r] = (gm < N_NODES)
                    ? *reinterpret_cast<const float4*>(
                          x + (size_t)gm * D_IN + k0 + q * 4)
                    : make_float4(0.f, 0.f, 0.f, 0.f);
                wn[r] = *reinterpret_cast<const float4*>(
                    w + (size_t)m * D_IN + k0 + q * 4);
            }
        }

#pragma unroll
        for (int ks = 0; ks < 4; ks++) {
            const int kk = ks * 8;
            uint32_t a[2][4];
#pragma unroll
            for (int mt = 0; mt < 2; mt++) {
                int mr = warp_m * 32 + mt * 16 + (lane >> 2);
                int kc = kk + (lane & 3);
                a[mt][0] = As[mr * LDS_PAD + kc];
                a[mt][1] = As[(mr + 8) * LDS_PAD + kc];
                a[mt][2] = As[mr * LDS_PAD + kc + 4];
                a[mt][3] = As[(mr + 8) * LDS_PAD + kc + 4];
            }
#pragma unroll
            for (int nt = 0; nt < 8; nt++) {
                int nr = warp_n * 64 + nt * 8 + (lane >> 2);
                uint32_t b0 = Bs[nr * LDS_PAD + kk + (lane & 3)];
                uint32_t b1 = Bs[nr * LDS_PAD + kk + (lane & 3) + 4];
                mma_tf32(acc[0][nt], a[0], b0, b1);
                mma_tf32(acc[1][nt], a[1], b0, b1);
            }
        }
        __syncthreads();

        if (more) {
#pragma unroll
            for (int r = 0; r < 4; r++) { xv[r] = xn[r]; wv[r] = wn[r]; }
        }
    }

#pragma unroll
    for (int mt = 0; mt < 2; mt++) {
        int r0 = m0 + warp_m * 32 + mt * 16 + (lane >> 2);
        int r1 = r0 + 8;
#pragma unroll
        for (int nt = 0; nt < 8; nt++) {
            int c0 = warp_n * 64 + nt * 8 + (lane & 3) * 2;
            if (r0 < N_NODES)
                *reinterpret_cast<float2*>(&g_seq[(size_t)r0 * D_OUT + c0]) =
                    make_float2(acc[mt][nt][0], acc[mt][nt][1]);
            if (r1 < N_NODES)
                *reinterpret_cast<float2*>(&g_seq[(size_t)r1 * D_OUT + c0]) =
                    make_float2(acc[mt][nt][2], acc[mt][nt][3]);
        }
    }
}

// ---------------------------------------------------------------------------
// CSR build step 1: zero counts
// ---------------------------------------------------------------------------
__global__ void gcn_zero_counts_kernel()
{
    int i = blockIdx.x * blockDim.x + threadIdx.x;
    if (i <= N_NODES) g_counts[i] = 0;
}

// ---------------------------------------------------------------------------
// CSR build step 2: histogram of edge_row
// ---------------------------------------------------------------------------
__global__ __launch_bounds__(256) void gcn_hist_kernel(
    const int* __restrict__ edge_row)
{
    int e = blockIdx.x * blockDim.x + threadIdx.x;
    if (e < N_EDGES) atomicAdd(&g_counts[edge_row[e]], 1);
}

// ---------------------------------------------------------------------------
// CSR build step 3: exclusive scan of counts (single block, 1024 threads,
// 40 elements/thread). Writes row_start[0..N] and cursor[0..N-1].
// ---------------------------------------------------------------------------
#define SCAN_THREADS 1024
#define SCAN_CHUNK   40   // 1024*40 = 40960 >= 40000

__global__ __launch_bounds__(SCAN_THREADS) void gcn_scan_kernel()
{
    __shared__ int warp_tot[32];

    const int t    = threadIdx.x;
    const int lane = t & 31;
    const int wid  = t >> 5;

    // local sum of this thread's chunk
    int local[SCAN_CHUNK];
    int sum = 0;
#pragma unroll
    for (int j = 0; j < SCAN_CHUNK; j++) {
        int i = t * SCAN_CHUNK + j;
        int c = (i < N_NODES) ? g_counts[i] : 0;
        local[j] = c;
        sum += c;
    }

    // warp inclusive scan of sums
    int inc = sum;
#pragma unroll
    for (int o = 1; o < 32; o <<= 1) {
        int n = __shfl_up_sync(0xffffffffu, inc, o);
        if (lane >= o) inc += n;
    }
    if (lane == 31) warp_tot[wid] = inc;
    __syncthreads();

    // warp 0 scans the 32 warp totals (exclusive)
    if (wid == 0) {
        int v = warp_tot[lane];
        int winc = v;
#pragma unroll
        for (int o = 1; o < 32; o <<= 1) {
            int n = __shfl_up_sync(0xffffffffu, winc, o);
            if (lane >= o) winc += n;
        }
        warp_tot[lane] = winc - v;   // exclusive
    }
    __syncthreads();

    // exclusive prefix for this thread's chunk
    int running = warp_tot[wid] + (inc - sum);
#pragma unroll
    for (int j = 0; j < SCAN_CHUNK; j++) {
        int i = t * SCAN_CHUNK + j;
        if (i < N_NODES) {
            g_row_start[i] = running;
            g_cursor[i]    = running;
            running += local[j];
        }
    }
    if (t == SCAN_THREADS - 1) g_row_start[N_NODES] = running;  // == N_EDGES
}

// ---------------------------------------------------------------------------
// CSR build step 4: permute edges into row-sorted order (packed col+val)
// ---------------------------------------------------------------------------
__global__ __launch_bounds__(256) void gcn_permute_kernel(
    const float* __restrict__ edge_val,
    const int*   __restrict__ edge_row,
    const int*   __restrict__ edge_col)
{
    int e = blockIdx.x * blockDim.x + threadIdx.x;
    if (e >= N_EDGES) return;
    int row = edge_row[e];
    int pos = atomicAdd(&g_cursor[row], 1);
    g_sorted_cv[pos] = make_int2(edge_col[e], __float_as_int(edge_val[e]));
}

// ---------------------------------------------------------------------------
// Fused gather + bias + PReLU: one warp per row, lane owns a float4 slice.
// out[r] = prelu(bias + sum_e val_e * seq[col_e])
// ---------------------------------------------------------------------------
__global__ __launch_bounds__(256) void gcn_gather_kernel(
    const float* __restrict__ bias,
    const float* __restrict__ alpha,
    float*       __restrict__ out)
{
    const int warp = (blockIdx.x * blockDim.x + threadIdx.x) >> 5;
    if (warp >= N_NODES) return;
    const int lane = threadIdx.x & 31;

    const int e0 = g_row_start[warp];
    const int e1 = g_row_start[warp + 1];

    const float4* seq4 = reinterpret_cast<const float4*>(g_seq);

    float4 acc = make_float4(0.f, 0.f, 0.f, 0.f);

    int e = e0;
    // unroll by 4 for memory-level parallelism on the seq gathers
    for (; e + 4 <= e1; e += 4) {
        int2 cv0 = g_sorted_cv[e];
        int2 cv1 = g_sorted_cv[e + 1];
        int2 cv2 = g_sorted_cv[e + 2];
        int2 cv3 = g_sorted_cv[e + 3];
        float4 s0 = seq4[(size_t)cv0.x * (D_OUT / 4) + lane];
        float4 s1 = seq4[(size_t)cv1.x * (D_OUT / 4) + lane];
        float4 s2 = seq4[(size_t)cv2.x * (D_OUT / 4) + lane];
        float4 s3 = seq4[(size_t)cv3.x * (D_OUT / 4) + lane];
        float v0 = __int_as_float(cv0.y), v1 = __int_as_float(cv1.y);
        float v2 = __int_as_float(cv2.y), v3 = __int_as_float(cv3.y);
        acc.x = fmaf(v0, s0.x, acc.x); acc.y = fmaf(v0, s0.y, acc.y);
        acc.z = fmaf(v0, s0.z, acc.z); acc.w = fmaf(v0, s0.w, acc.w);
        acc.x = fmaf(v1, s1.x, acc.x); acc.y = fmaf(v1, s1.y, acc.y);
        acc.z = fmaf(v1, s1.z, acc.z); acc.w = fmaf(v1, s1.w, acc.w);
        acc.x = fmaf(v2, s2.x, acc.x); acc.y = fmaf(v2, s2.y, acc.y);
        acc.z = fmaf(v2, s2.z, acc.z); acc.w = fmaf(v2, s2.w, acc.w);
        acc.x = fmaf(v3, s3.x, acc.x); acc.y = fmaf(v3, s3.y, acc.y);
        acc.z = fmaf(v3, s3.z, acc.z); acc.w = fmaf(v3, s3.w, acc.w);
    }
    for (; e < e1; e++) {
        int2 cv = g_sorted_cv[e];
        float4 s = seq4[(size_t)cv.x * (D_OUT / 4) + lane];
        float v  = __int_as_float(cv.y);
        acc.x = fmaf(v, s.x, acc.x); acc.y = fmaf(v, s.y, acc.y);
        acc.z = fmaf(v, s.z, acc.z); acc.w = fmaf(v, s.w, acc.w);
    }

    // bias + PReLU
    float4 b = *reinterpret_cast<const float4*>(bias + lane * 4);
    float  a = __ldg(alpha);
    acc.x += b.x; acc.y += b.y; acc.z += b.z; acc.w += b.w;
    acc.x = acc.x > 0.f ? acc.x : a * acc.x;
    acc.y = acc.y > 0.f ? acc.y : a * acc.y;
    acc.z = acc.z > 0.f ? acc.z : a * acc.z;
    acc.w = acc.w > 0.f ? acc.w : a * acc.w;

    reinterpret_cast<float4*>(out)[(size_t)warp * (D_OUT / 4) + lane] = acc;
}

// ---------------------------------------------------------------------------
// Inputs (metadata order): x, weight, bias, alpha, edge_val, edge_row, edge_col
// Output: float32 [40000, 128]
// ---------------------------------------------------------------------------
extern "C" void kernel_launch(void* const* d_in, const int* in_sizes, int n_in,
                              void* d_out, int out_size)
{
    const float* x        = (const float*)d_in[0];
    const float* weight   = (const float*)d_in[1];
    const float* bias     = (const float*)d_in[2];
    const float* alpha    = (const float*)d_in[3];
    const float* edge_val = (const float*)d_in[4];
    const int*   edge_row = (const int*)  d_in[5];
    const int*   edge_col = (const int*)  d_in[6];
    float*       out      = (float*)d_out;

    (void)in_sizes; (void)n_in; (void)out_size;

    // 1) seq = x @ W^T  (tensor cores, tf32)
    gcn_gemm_tf32_kernel<<<(N_NODES + 127) / 128, 256>>>(x, weight);

    // 2) CSR build: counts -> scan -> permute
    gcn_zero_counts_kernel<<<(N_NODES + 256) / 256, 256>>>();
    gcn_hist_kernel<<<(N_EDGES + 255) / 256, 256>>>(edge_row);
    gcn_scan_kernel<<<1, SCAN_THREADS>>>();
    gcn_permute_kernel<<<(N_EDGES + 255) / 256, 256>>>(
        edge_val, edge_row, edge_col);

    // 3) fused gather + bias + PReLU (one warp per node row)
    const long long gthreads = (long long)N_NODES * 32;
    gcn_gather_kernel<<<(unsigned)((gthreads + 255) / 256), 256>>>(
        bias, alpha, out);
}

// round 7
// speedup vs baseline: 1.3707x; 1.3707x over previous
#include <cuda_runtime.h>
#include <cstdint>

#define N_NODES 40000
#define N_EDGES 640000
#define D_IN    512
#define D_OUT   128

#define NB_SCAN ((N_NODES + 255) / 256)   // 157 blocks over the counts array

// ---------------------------------------------------------------------------
// __device__ scratch (allocation-free rule)
// ---------------------------------------------------------------------------
__device__ __align__(16) float g_seq[(size_t)N_NODES * D_OUT];  // 20.5 MB
__device__ int  g_counts[N_NODES + 1];
__device__ int  g_row_start[N_NODES + 1];
__device__ int  g_cursor[N_NODES + 1];
__device__ int  g_partials[NB_SCAN];
__device__ __align__(8) int2 g_sorted_cv[N_EDGES];  // {col, float_bits(val)}

// ---------------------------------------------------------------------------
// tf32 helpers
// ---------------------------------------------------------------------------
__device__ __forceinline__ uint32_t f2tf32(float f) {
    uint32_t u;
    asm("cvt.rna.tf32.f32 %0, %1;" : "=r"(u) : "f"(f));
    return u;
}

__device__ __forceinline__ void mma_tf32(float* c, const uint32_t* a,
                                         uint32_t b0, uint32_t b1) {
    asm volatile(
        "mma.sync.aligned.m16n8k8.row.col.f32.tf32.tf32.f32 "
        "{%0,%1,%2,%3}, {%4,%5,%6,%7}, {%8,%9}, {%0,%1,%2,%3};"
        : "+f"(c[0]), "+f"(c[1]), "+f"(c[2]), "+f"(c[3])
        : "r"(a[0]), "r"(a[1]), "r"(a[2]), "r"(a[3]), "r"(b0), "r"(b1));
}

// ---------------------------------------------------------------------------
// GEMM: seq[n][o] = sum_k x[n][k] * w[o][k]   (tf32 tensor cores)
// 128x128 block tile, BK=32, 256 threads = 8 warps (4x2), warp tile 32x64.
// ---------------------------------------------------------------------------
#define BK 32
#define LDS_PAD 36   // 36*4 = 144 bytes per row, 144 % 16 == 0

__global__ __launch_bounds__(256, 1) void gcn_gemm_tf32_kernel(
    const float* __restrict__ x, const float* __restrict__ w)
{
    __shared__ uint32_t As[128 * LDS_PAD];   // [m][k] tf32
    __shared__ uint32_t Bs[128 * LDS_PAD];   // [n][k] tf32

    const int tid    = threadIdx.x;
    const int lane   = tid & 31;
    const int wid    = tid >> 5;
    const int warp_m = wid & 3;
    const int warp_n = wid >> 2;
    const int m0     = blockIdx.x * 128;

    const int q    = tid & 7;
    const int mrow = tid >> 3;

    float acc[2][8][4];
#pragma unroll
    for (int mt = 0; mt < 2; mt++)
#pragma unroll
        for (int nt = 0; nt < 8; nt++)
#pragma unroll
            for (int j = 0; j < 4; j++) acc[mt][nt][j] = 0.f;

    float4 xv[4], wv[4];

#pragma unroll
    for (int r = 0; r < 4; r++) {
        int m  = mrow + r * 32;
        int gm = m0 + m;
        xv[r] = (gm < N_NODES)
            ? *reinterpret_cast<const float4*>(x + (size_t)gm * D_IN + q * 4)
            : make_float4(0.f, 0.f, 0.f, 0.f);
        wv[r] = *reinterpret_cast<const float4*>(w + (size_t)m * D_IN + q * 4);
    }

#pragma unroll 1
    for (int kt = 0; kt < D_IN / BK; kt++) {
#pragma unroll
        for (int r = 0; r < 4; r++) {
            int m    = mrow + r * 32;
            int base = m * LDS_PAD + q * 4;
            uint4 ta = make_uint4(f2tf32(xv[r].x), f2tf32(xv[r].y),
                                  f2tf32(xv[r].z), f2tf32(xv[r].w));
            uint4 tb = make_uint4(f2tf32(wv[r].x), f2tf32(wv[r].y),
                                  f2tf32(wv[r].z), f2tf32(wv[r].w));
            *reinterpret_cast<uint4*>(&As[base]) = ta;
            *reinterpret_cast<uint4*>(&Bs[base]) = tb;
        }
        __syncthreads();

        const bool more = (kt + 1) < (D_IN / BK);
        float4 xn[4], wn[4];
        if (more) {
            int k0 = (kt + 1) * BK;
#pragma unroll
            for (int r = 0; r < 4; r++) {
                int m  = mrow + r * 32;
                int gm = m0 + m;
                xn[r] = (gm < N_NODES)
                    ? *reinterpret_cast<const float4*>(
                          x + (size_t)gm * D_IN + k0 + q * 4)
                    : make_float4(0.f, 0.f, 0.f, 0.f);
                wn[r] = *reinterpret_cast<const float4*>(
                    w + (size_t)m * D_IN + k0 + q * 4);
            }
        }

#pragma unroll
        for (int ks = 0; ks < 4; ks++) {
            const int kk = ks * 8;
            uint32_t a[2][4];
#pragma unroll
            for (int mt = 0; mt < 2; mt++) {
                int mr = warp_m * 32 + mt * 16 + (lane >> 2);
                int kc = kk + (lane & 3);
                a[mt][0] = As[mr * LDS_PAD + kc];
                a[mt][1] = As[(mr + 8) * LDS_PAD + kc];
                a[mt][2] = As[mr * LDS_PAD + kc + 4];
                a[mt][3] = As[(mr + 8) * LDS_PAD + kc + 4];
            }
#pragma unroll
            for (int nt = 0; nt < 8; nt++) {
                int nr = warp_n * 64 + nt * 8 + (lane >> 2);
                uint32_t b0 = Bs[nr * LDS_PAD + kk + (lane & 3)];
                uint32_t b1 = Bs[nr * LDS_PAD + kk + (lane & 3) + 4];
                mma_tf32(acc[0][nt], a[0], b0, b1);
                mma_tf32(acc[1][nt], a[1], b0, b1);
            }
        }
        __syncthreads();

        if (more) {
#pragma unroll
            for (int r = 0; r < 4; r++) { xv[r] = xn[r]; wv[r] = wn[r]; }
        }
    }

#pragma unroll
    for (int mt = 0; mt < 2; mt++) {
        int r0 = m0 + warp_m * 32 + mt * 16 + (lane >> 2);
        int r1 = r0 + 8;
#pragma unroll
        for (int nt = 0; nt < 8; nt++) {
            int c0 = warp_n * 64 + nt * 8 + (lane & 3) * 2;
            if (r0 < N_NODES)
                *reinterpret_cast<float2*>(&g_seq[(size_t)r0 * D_OUT + c0]) =
                    make_float2(acc[mt][nt][0], acc[mt][nt][1]);
            if (r1 < N_NODES)
                *reinterpret_cast<float2*>(&g_seq[(size_t)r1 * D_OUT + c0]) =
                    make_float2(acc[mt][nt][2], acc[mt][nt][3]);
        }
    }
}

// ---------------------------------------------------------------------------
// CSR build step 1: zero counts
// ---------------------------------------------------------------------------
__global__ void gcn_zero_counts_kernel()
{
    int i = blockIdx.x * blockDim.x + threadIdx.x;
    if (i <= N_NODES) g_counts[i] = 0;
}

// ---------------------------------------------------------------------------
// CSR build step 2: histogram of edge_row
// ---------------------------------------------------------------------------
__global__ __launch_bounds__(256) void gcn_hist_kernel(
    const int* __restrict__ edge_row)
{
    int e = blockIdx.x * blockDim.x + threadIdx.x;
    if (e < N_EDGES) atomicAdd(&g_counts[edge_row[e]], 1);
}

// ---------------------------------------------------------------------------
// CSR build step 3: exclusive scan of counts — 3-phase, full-chip.
// Phase A: per-block reduction of 256 counts -> g_partials[b]
// Phase B: single-block exclusive scan of the 157 partials
// Phase C: per-block exclusive scan + partial offset -> row_start/cursor
// ---------------------------------------------------------------------------
__global__ __launch_bounds__(256) void gcn_scan_phaseA_kernel()
{
    __shared__ int s_w[8];
    const int t    = threadIdx.x;
    const int lane = t & 31;
    const int wid  = t >> 5;
    const int i    = blockIdx.x * 256 + t;

    int c = (i < N_NODES) ? g_counts[i] : 0;
#pragma unroll
    for (int o = 16; o > 0; o >>= 1)
        c += __shfl_down_sync(0xffffffffu, c, o);
    if (lane == 0) s_w[wid] = c;
    __syncthreads();
    if (t == 0) {
        int tot = 0;
#pragma unroll
        for (int j = 0; j < 8; j++) tot += s_w[j];
        g_partials[blockIdx.x] = tot;
    }
}

__global__ __launch_bounds__(256) void gcn_scan_phaseB_kernel()
{
    __shared__ int s_w[8];
    const int t    = threadIdx.x;
    const int lane = t & 31;
    const int wid  = t >> 5;

    int v   = (t < NB_SCAN) ? g_partials[t] : 0;
    int inc = v;
#pragma unroll
    for (int o = 1; o < 32; o <<= 1) {
        int n = __shfl_up_sync(0xffffffffu, inc, o);
        if (lane >= o) inc += n;
    }
    if (lane == 31) s_w[wid] = inc;
    __syncthreads();
    if (wid == 0 && lane < 8) {
        int wv = s_w[lane];
        int wi = wv;
#pragma unroll
        for (int o = 1; o < 8; o <<= 1) {
            int n = __shfl_up_sync(0x000000ffu, wi, o);
            if (lane >= o) wi += n;
        }
        s_w[lane] = wi - wv;    // exclusive
    }
    __syncthreads();
    if (t < NB_SCAN) g_partials[t] = inc - v + s_w[wid];  // exclusive
}

__global__ __launch_bounds__(256) void gcn_scan_phaseC_kernel()
{
    __shared__ int s_w[8];
    const int t    = threadIdx.x;
    const int lane = t & 31;
    const int wid  = t >> 5;
    const int i    = blockIdx.x * 256 + t;

    int c   = (i < N_NODES) ? g_counts[i] : 0;
    int inc = c;
#pragma unroll
    for (int o = 1; o < 32; o <<= 1) {
        int n = __shfl_up_sync(0xffffffffu, inc, o);
        if (lane >= o) inc += n;
    }
    if (lane == 31) s_w[wid] = inc;
    __syncthreads();
    if (wid == 0 && lane < 8) {
        int wv = s_w[lane];
        int wi = wv;
#pragma unroll
        for (int o = 1; o < 8; o <<= 1) {
            int n = __shfl_up_sync(0x000000ffu, wi, o);
            if (lane >= o) wi += n;
        }
        s_w[lane] = wi - wv;    // exclusive over warp sums
    }
    __syncthreads();

    if (i < N_NODES) {
        int excl = (inc - c) + s_w[wid] + g_partials[blockIdx.x];
        g_row_start[i] = excl;
        g_cursor[i]    = excl;
    }
    // total edge count is a static invariant: every edge lands in some row
    if (blockIdx.x == 0 && t == 0) g_row_start[N_NODES] = N_EDGES;
}

// ---------------------------------------------------------------------------
// CSR build step 4: permute edges into row-sorted order (packed col+val)
// ---------------------------------------------------------------------------
__global__ __launch_bounds__(256) void gcn_permute_kernel(
    const float* __restrict__ edge_val,
    const int*   __restrict__ edge_row,
    const int*   __restrict__ edge_col)
{
    int e = blockIdx.x * blockDim.x + threadIdx.x;
    if (e >= N_EDGES) return;
    int row = edge_row[e];
    int pos = atomicAdd(&g_cursor[row], 1);
    g_sorted_cv[pos] = make_int2(edge_col[e], __float_as_int(edge_val[e]));
}

// ---------------------------------------------------------------------------
// Fused gather + bias + PReLU: one warp per row, lane owns a float4 slice.
// out[r] = prelu(bias + sum_e val_e * seq[col_e])
// ---------------------------------------------------------------------------
__global__ __launch_bounds__(256) void gcn_gather_kernel(
    const float* __restrict__ bias,
    const float* __restrict__ alpha,
    float*       __restrict__ out)
{
    const int warp = (blockIdx.x * blockDim.x + threadIdx.x) >> 5;
    if (warp >= N_NODES) return;
    const int lane = threadIdx.x & 31;

    const int e0 = g_row_start[warp];
    const int e1 = g_row_start[warp + 1];

    const float4* seq4 = reinterpret_cast<const float4*>(g_seq);

    float4 acc = make_float4(0.f, 0.f, 0.f, 0.f);

    int e = e0;
    // unroll by 4 for memory-level parallelism on the seq gathers
    for (; e + 4 <= e1; e += 4) {
        int2 cv0 = g_sorted_cv[e];
        int2 cv1 = g_sorted_cv[e + 1];
        int2 cv2 = g_sorted_cv[e + 2];
        int2 cv3 = g_sorted_cv[e + 3];
        float4 s0 = seq4[(size_t)cv0.x * (D_OUT / 4) + lane];
        float4 s1 = seq4[(size_t)cv1.x * (D_OUT / 4) + lane];
        float4 s2 = seq4[(size_t)cv2.x * (D_OUT / 4) + lane];
        float4 s3 = seq4[(size_t)cv3.x * (D_OUT / 4) + lane];
        float v0 = __int_as_float(cv0.y), v1 = __int_as_float(cv1.y);
        float v2 = __int_as_float(cv2.y), v3 = __int_as_float(cv3.y);
        acc.x = fmaf(v0, s0.x, acc.x); acc.y = fmaf(v0, s0.y, acc.y);
        acc.z = fmaf(v0, s0.z, acc.z); acc.w = fmaf(v0, s0.w, acc.w);
        acc.x = fmaf(v1, s1.x, acc.x); acc.y = fmaf(v1, s1.y, acc.y);
        acc.z = fmaf(v1, s1.z, acc.z); acc.w = fmaf(v1, s1.w, acc.w);
        acc.x = fmaf(v2, s2.x, acc.x); acc.y = fmaf(v2, s2.y, acc.y);
        acc.z = fmaf(v2, s2.z, acc.z); acc.w = fmaf(v2, s2.w, acc.w);
        acc.x = fmaf(v3, s3.x, acc.x); acc.y = fmaf(v3, s3.y, acc.y);
        acc.z = fmaf(v3, s3.z, acc.z); acc.w = fmaf(v3, s3.w, acc.w);
    }
    for (; e < e1; e++) {
        int2 cv = g_sorted_cv[e];
        float4 s = seq4[(size_t)cv.x * (D_OUT / 4) + lane];
        float v  = __int_as_float(cv.y);
        acc.x = fmaf(v, s.x, acc.x); acc.y = fmaf(v, s.y, acc.y);
        acc.z = fmaf(v, s.z, acc.z); acc.w = fmaf(v, s.w, acc.w);
    }

    // bias + PReLU
    float4 b = *reinterpret_cast<const float4*>(bias + lane * 4);
    float  a = __ldg(alpha);
    acc.x += b.x; acc.y += b.y; acc.z += b.z; acc.w += b.w;
    acc.x = acc.x > 0.f ? acc.x : a * acc.x;
    acc.y = acc.y > 0.f ? acc.y : a * acc.y;
    acc.z = acc.z > 0.f ? acc.z : a * acc.z;
    acc.w = acc.w > 0.f ? acc.w : a * acc.w;

    reinterpret_cast<float4*>(out)[(size_t)warp * (D_OUT / 4) + lane] = acc;
}

// ---------------------------------------------------------------------------
// Inputs (metadata order): x, weight, bias, alpha, edge_val, edge_row, edge_col
// Output: float32 [40000, 128]
// ---------------------------------------------------------------------------
extern "C" void kernel_launch(void* const* d_in, const int* in_sizes, int n_in,
                              void* d_out, int out_size)
{
    const float* x        = (const float*)d_in[0];
    const float* weight   = (const float*)d_in[1];
    const float* bias     = (const float*)d_in[2];
    const float* alpha    = (const float*)d_in[3];
    const float* edge_val = (const float*)d_in[4];
    const int*   edge_row = (const int*)  d_in[5];
    const int*   edge_col = (const int*)  d_in[6];
    float*       out      = (float*)d_out;

    (void)in_sizes; (void)n_in; (void)out_size;

    // 1) seq = x @ W^T  (tensor cores, tf32)
    gcn_gemm_tf32_kernel<<<(N_NODES + 127) / 128, 256>>>(x, weight);

    // 2) CSR build: counts -> 3-phase scan -> permute
    gcn_zero_counts_kernel<<<(N_NODES + 256) / 256, 256>>>();
    gcn_hist_kernel<<<(N_EDGES + 255) / 256, 256>>>(edge_row);
    gcn_scan_phaseA_kernel<<<NB_SCAN, 256>>>();
    gcn_scan_phaseB_kernel<<<1, 256>>>();
    gcn_scan_phaseC_kernel<<<NB_SCAN, 256>>>();
    gcn_permute_kernel<<<(N_EDGES + 255) / 256, 256>>>(
        edge_val, edge_row, edge_col);

    // 3) fused gather + bias + PReLU (one warp per node row)
    const long long gthreads = (long long)N_NODES * 32;
    gcn_gather_kernel<<<(unsigned)((gthreads + 255) / 256), 256>>>(
        bias, alpha, out);
}

// round 12
// speedup vs baseline: 1.4847x; 1.0832x over previous
#include <cuda_runtime.h>
#include <cstdint>

#define N_NODES 40000
#define N_EDGES 640000
#define D_IN    512
#define D_OUT   128

#define NB_SCAN  ((N_NODES + 255) / 256)    // 157 blocks over counts
#define NB_GEMM  ((N_NODES + 127) / 128)    // 313 GEMM tiles
#define HIST_EPB 2048                       // edges per hist block
#define NB_HIST  ((N_EDGES + HIST_EPB - 1) / HIST_EPB)   // 313

// ---------------------------------------------------------------------------
// __device__ scratch (allocation-free rule)
// ---------------------------------------------------------------------------
__device__ __align__(16) float g_seq[(size_t)N_NODES * D_OUT];  // 20.5 MB
__device__ int  g_counts[N_NODES + 1];
__device__ int  g_row_start[N_NODES + 1];
__device__ int  g_cursor[N_NODES + 1];
__device__ int  g_partials[NB_SCAN];
__device__ __align__(8) int2 g_sorted_cv[N_EDGES];  // {col, float_bits(val)}

// ---------------------------------------------------------------------------
// tf32 helpers
// ---------------------------------------------------------------------------
__device__ __forceinline__ uint32_t f2tf32(float f) {
    uint32_t u;
    asm("cvt.rna.tf32.f32 %0, %1;" : "=r"(u) : "f"(f));
    return u;
}

__device__ __forceinline__ void mma_tf32(float* c, const uint32_t* a,
                                         uint32_t b0, uint32_t b1) {
    asm volatile(
        "mma.sync.aligned.m16n8k8.row.col.f32.tf32.tf32.f32 "
        "{%0,%1,%2,%3}, {%4,%5,%6,%7}, {%8,%9}, {%0,%1,%2,%3};"
        : "+f"(c[0]), "+f"(c[1]), "+f"(c[2]), "+f"(c[3])
        : "r"(a[0]), "r"(a[1]), "r"(a[2]), "r"(a[3]), "r"(b0), "r"(b1));
}

// ---------------------------------------------------------------------------
// Fused GEMM + histogram.
//   blocks [0, NB_GEMM):        seq = x @ W^T  (tf32 tensor cores)
//   blocks [NB_GEMM, +NB_HIST): histogram of edge_row into g_counts
// The hist blocks slot into the GEMM's second wave, hiding their cost.
// ---------------------------------------------------------------------------
#define BK 32
#define LDS_PAD 36   // 36*4 = 144 bytes per row, 144 % 16 == 0

__global__ __launch_bounds__(256, 1) void gcn_gemm_hist_kernel(
    const float* __restrict__ x, const float* __restrict__ w,
    const int* __restrict__ edge_row)
{
    if (blockIdx.x >= NB_GEMM) {
        // ---- histogram path ----
        int base = (blockIdx.x - NB_GEMM) * HIST_EPB + threadIdx.x;
#pragma unroll
        for (int j = 0; j < HIST_EPB / 256; j++) {
            int e = base + j * 256;
            if (e < N_EDGES) atomicAdd(&g_counts[edge_row[e]], 1);
        }
        return;
    }

    // ---- GEMM path ----
    __shared__ uint32_t As[128 * LDS_PAD];   // [m][k] tf32
    __shared__ uint32_t Bs[128 * LDS_PAD];   // [n][k] tf32

    const int tid    = threadIdx.x;
    const int lane   = tid & 31;
    const int wid    = tid >> 5;
    const int warp_m = wid & 3;
    const int warp_n = wid >> 2;
    const int m0     = blockIdx.x * 128;

    const int q    = tid & 7;
    const int mrow = tid >> 3;

    float acc[2][8][4];
#pragma unroll
    for (int mt = 0; mt < 2; mt++)
#pragma unroll
        for (int nt = 0; nt < 8; nt++)
#pragma unroll
            for (int j = 0; j < 4; j++) acc[mt][nt][j] = 0.f;

    float4 xv[4], wv[4];

#pragma unroll
    for (int r = 0; r < 4; r++) {
        int m  = mrow + r * 32;
        int gm = m0 + m;
        xv[r] = (gm < N_NODES)
            ? *reinterpret_cast<const float4*>(x + (size_t)gm * D_IN + q * 4)
            : make_float4(0.f, 0.f, 0.f, 0.f);
        wv[r] = *reinterpret_cast<const float4*>(w + (size_t)m * D_IN + q * 4);
    }

#pragma unroll 1
    for (int kt = 0; kt < D_IN / BK; kt++) {
#pragma unroll
        for (int r = 0; r < 4; r++) {
            int m    = mrow + r * 32;
            int base = m * LDS_PAD + q * 4;
            uint4 ta = make_uint4(f2tf32(xv[r].x), f2tf32(xv[r].y),
                                  f2tf32(xv[r].z), f2tf32(xv[r].w));
            uint4 tb = make_uint4(f2tf32(wv[r].x), f2tf32(wv[r].y),
                                  f2tf32(wv[r].z), f2tf32(wv[r].w));
            *reinterpret_cast<uint4*>(&As[base]) = ta;
            *reinterpret_cast<uint4*>(&Bs[base]) = tb;
        }
        __syncthreads();

        const bool more = (kt + 1) < (D_IN / BK);
        float4 xn[4], wn[4];
        if (more) {
            int k0 = (kt + 1) * BK;
#pragma unroll
            for (int r = 0; r < 4; r++) {
                int m  = mrow + r * 32;
                int gm = m0 + m;
                xn[r] = (gm < N_NODES)
                    ? *reinterpret_cast<const float4*>(
                          x + (size_t)gm * D_IN + k0 + q * 4)
                    : make_float4(0.f, 0.f, 0.f, 0.f);
                wn[r] = *reinterpret_cast<const float4*>(
                    w + (size_t)m * D_IN + k0 + q * 4);
            }
        }

#pragma unroll
        for (int ks = 0; ks < 4; ks++) {
            const int kk = ks * 8;
            uint32_t a[2][4];
#pragma unroll
            for (int mt = 0; mt < 2; mt++) {
                int mr = warp_m * 32 + mt * 16 + (lane >> 2);
                int kc = kk + (lane & 3);
                a[mt][0] = As[mr * LDS_PAD + kc];
                a[mt][1] = As[(mr + 8) * LDS_PAD + kc];
                a[mt][2] = As[mr * LDS_PAD + kc + 4];
                a[mt][3] = As[(mr + 8) * LDS_PAD + kc + 4];
            }
#pragma unroll
            for (int nt = 0; nt < 8; nt++) {
                int nr = warp_n * 64 + nt * 8 + (lane >> 2);
                uint32_t b0 = Bs[nr * LDS_PAD + kk + (lane & 3)];
                uint32_t b1 = Bs[nr * LDS_PAD + kk + (lane & 3) + 4];
                mma_tf32(acc[0][nt], a[0], b0, b1);
                mma_tf32(acc[1][nt], a[1], b0, b1);
            }
        }
        __syncthreads();

        if (more) {
#pragma unroll
            for (int r = 0; r < 4; r++) { xv[r] = xn[r]; wv[r] = wn[r]; }
        }
    }

#pragma unroll
    for (int mt = 0; mt < 2; mt++) {
        int r0 = m0 + warp_m * 32 + mt * 16 + (lane >> 2);
        int r1 = r0 + 8;
#pragma unroll
        for (int nt = 0; nt < 8; nt++) {
            int c0 = warp_n * 64 + nt * 8 + (lane & 3) * 2;
            if (r0 < N_NODES)
                *reinterpret_cast<float2*>(&g_seq[(size_t)r0 * D_OUT + c0]) =
                    make_float2(acc[mt][nt][0], acc[mt][nt][1]);
            if (r1 < N_NODES)
                *reinterpret_cast<float2*>(&g_seq[(size_t)r1 * D_OUT + c0]) =
                    make_float2(acc[mt][nt][2], acc[mt][nt][3]);
        }
    }
}

// ---------------------------------------------------------------------------
// zero counts (must precede the fused kernel's histogram)
// ---------------------------------------------------------------------------
__global__ void gcn_zero_counts_kernel()
{
    int i = blockIdx.x * blockDim.x + threadIdx.x;
    if (i <= N_NODES) g_counts[i] = 0;
}

// ---------------------------------------------------------------------------
// 3-phase exclusive scan of counts
// ---------------------------------------------------------------------------
__global__ __launch_bounds__(256) void gcn_scan_phaseA_kernel()
{
    __shared__ int s_w[8];
    const int t    = threadIdx.x;
    const int lane = t & 31;
    const int wid  = t >> 5;
    const int i    = blockIdx.x * 256 + t;

    int c = (i < N_NODES) ? g_counts[i] : 0;
#pragma unroll
    for (int o = 16; o > 0; o >>= 1)
        c += __shfl_down_sync(0xffffffffu, c, o);
    if (lane == 0) s_w[wid] = c;
    __syncthreads();
    if (t == 0) {
        int tot = 0;
#pragma unroll
        for (int j = 0; j < 8; j++) tot += s_w[j];
        g_partials[blockIdx.x] = tot;
    }
}

__global__ __launch_bounds__(256) void gcn_scan_phaseB_kernel()
{
    __shared__ int s_w[8];
    const int t    = threadIdx.x;
    const int lane = t & 31;
    const int wid  = t >> 5;

    int v   = (t < NB_SCAN) ? g_partials[t] : 0;
    int inc = v;
#pragma unroll
    for (int o = 1; o < 32; o <<= 1) {
        int n = __shfl_up_sync(0xffffffffu, inc, o);
        if (lane >= o) inc += n;
    }
    if (lane == 31) s_w[wid] = inc;
    __syncthreads();
    if (wid == 0 && lane < 8) {
        int wv = s_w[lane];
        int wi = wv;
#pragma unroll
        for (int o = 1; o < 8; o <<= 1) {
            int n = __shfl_up_sync(0x000000ffu, wi, o);
            if (lane >= o) wi += n;
        }
        s_w[lane] = wi - wv;    // exclusive
    }
    __syncthreads();
    if (t < NB_SCAN) g_partials[t] = inc - v + s_w[wid];  // exclusive
}

__global__ __launch_bounds__(256) void gcn_scan_phaseC_kernel()
{
    __shared__ int s_w[8];
    const int t    = threadIdx.x;
    const int lane = t & 31;
    const int wid  = t >> 5;
    const int i    = blockIdx.x * 256 + t;

    int c   = (i < N_NODES) ? g_counts[i] : 0;
    int inc = c;
#pragma unroll
    for (int o = 1; o < 32; o <<= 1) {
        int n = __shfl_up_sync(0xffffffffu, inc, o);
        if (lane >= o) inc += n;
    }
    if (lane == 31) s_w[wid] = inc;
    __syncthreads();
    if (wid == 0 && lane < 8) {
        int wv = s_w[lane];
        int wi = wv;
#pragma unroll
        for (int o = 1; o < 8; o <<= 1) {
            int n = __shfl_up_sync(0x000000ffu, wi, o);
            if (lane >= o) wi += n;
        }
        s_w[lane] = wi - wv;    // exclusive over warp sums
    }
    __syncthreads();

    if (i < N_NODES) {
        int excl = (inc - c) + s_w[wid] + g_partials[blockIdx.x];
        g_row_start[i] = excl;
        g_cursor[i]    = excl;
    }
    if (blockIdx.x == 0 && t == 0) g_row_start[N_NODES] = N_EDGES;
}

// ---------------------------------------------------------------------------
// permute edges into row-sorted order (packed col+val)
// ---------------------------------------------------------------------------
__global__ __launch_bounds__(256) void gcn_permute_kernel(
    const float* __restrict__ edge_val,
    const int*   __restrict__ edge_row,
    const int*   __restrict__ edge_col)
{
    int e = blockIdx.x * blockDim.x + threadIdx.x;
    if (e >= N_EDGES) return;
    int row = edge_row[e];
    int pos = atomicAdd(&g_cursor[row], 1);
    g_sorted_cv[pos] = make_int2(edge_col[e], __float_as_int(edge_val[e]));
}

// ---------------------------------------------------------------------------
// Fused gather + bias + PReLU: one warp per row, lane owns a float4 slice.
// Unroll-8 main loop for MLP depth (avg row = 16 edges -> 2 iterations).
// ---------------------------------------------------------------------------
__global__ __launch_bounds__(256) void gcn_gather_kernel(
    const float* __restrict__ bias,
    const float* __restrict__ alpha,
    float*       __restrict__ out)
{
    const int warp = (blockIdx.x * blockDim.x + threadIdx.x) >> 5;
    if (warp >= N_NODES) return;
    const int lane = threadIdx.x & 31;

    const int e0 = g_row_start[warp];
    const int e1 = g_row_start[warp + 1];

    const float4* seq4 = reinterpret_cast<const float4*>(g_seq);

    float4 acc = make_float4(0.f, 0.f, 0.f, 0.f);

    int e = e0;
    for (; e + 8 <= e1; e += 8) {
        int2   cv[8];
        float4 s[8];
#pragma unroll
        for (int j = 0; j < 8; j++) cv[j] = g_sorted_cv[e + j];
#pragma unroll
        for (int j = 0; j < 8; j++)
            s[j] = seq4[(size_t)cv[j].x * (D_OUT / 4) + lane];
#pragma unroll
        for (int j = 0; j < 8; j++) {
            float v = __int_as_float(cv[j].y);
            acc.x = fmaf(v, s[j].x, acc.x);
            acc.y = fmaf(v, s[j].y, acc.y);
            acc.z = fmaf(v, s[j].z, acc.z);
            acc.w = fmaf(v, s[j].w, acc.w);
        }
    }
    if (e + 4 <= e1) {
        int2   cv[4];
        float4 s[4];
#pragma unroll
        for (int j = 0; j < 4; j++) cv[j] = g_sorted_cv[e + j];
#pragma unroll
        for (int j = 0; j < 4; j++)
            s[j] = seq4[(size_t)cv[j].x * (D_OUT / 4) + lane];
#pragma unroll
        for (int j = 0; j < 4; j++) {
            float v = __int_as_float(cv[j].y);
            acc.x = fmaf(v, s[j].x, acc.x);
            acc.y = fmaf(v, s[j].y, acc.y);
            acc.z = fmaf(v, s[j].z, acc.z);
            acc.w = fmaf(v, s[j].w, acc.w);
        }
        e += 4;
    }
    for (; e < e1; e++) {
        int2 cv = g_sorted_cv[e];
        float4 s = seq4[(size_t)cv.x * (D_OUT / 4) + lane];
        float v  = __int_as_float(cv.y);
        acc.x = fmaf(v, s.x, acc.x); acc.y = fmaf(v, s.y, acc.y);
        acc.z = fmaf(v, s.z, acc.z); acc.w = fmaf(v, s.w, acc.w);
    }

    // bias + PReLU
    float4 b = *reinterpret_cast<const float4*>(bias + lane * 4);
    float  a = __ldg(alpha);
    acc.x += b.x; acc.y += b.y; acc.z += b.z; acc.w += b.w;
    acc.x = acc.x > 0.f ? acc.x : a * acc.x;
    acc.y = acc.y > 0.f ? acc.y : a * acc.y;
    acc.z = acc.z > 0.f ? acc.z : a * acc.z;
    acc.w = acc.w > 0.f ? acc.w : a * acc.w;

    reinterpret_cast<float4*>(out)[(size_t)warp * (D_OUT / 4) + lane] = acc;
}

// ---------------------------------------------------------------------------
// Inputs (metadata order): x, weight, bias, alpha, edge_val, edge_row, edge_col
// Output: float32 [40000, 128]
// ---------------------------------------------------------------------------
extern "C" void kernel_launch(void* const* d_in, const int* in_sizes, int n_in,
                              void* d_out, int out_size)
{
    const float* x        = (const float*)d_in[0];
    const float* weight   = (const float*)d_in[1];
    const float* bias     = (const float*)d_in[2];
    const float* alpha    = (const float*)d_in[3];
    const float* edge_val = (const float*)d_in[4];
    const int*   edge_row = (const int*)  d_in[5];
    const int*   edge_col = (const int*)  d_in[6];
    float*       out      = (float*)d_out;

    (void)in_sizes; (void)n_in; (void)out_size;

    // 1) zero counts (must precede fused hist)
    gcn_zero_counts_kernel<<<(N_NODES + 256) / 256, 256>>>();

    // 2) fused: seq = x @ W^T (tensor cores)  ||  histogram of edge_row
    gcn_gemm_hist_kernel<<<NB_GEMM + NB_HIST, 256>>>(x, weight, edge_row);

    // 3) 3-phase scan -> row_start/cursor
    gcn_scan_phaseA_kernel<<<NB_SCAN, 256>>>();
    gcn_scan_phaseB_kernel<<<1, 256>>>();
    gcn_scan_phaseC_kernel<<<NB_SCAN, 256>>>();

    // 4) permute edges into row order
    gcn_permute_kernel<<<(N_EDGES + 255) / 256, 256>>>(
        edge_val, edge_row, edge_col);

    // 5) fused gather + bias + PReLU (one warp per node row)
    const long long gthreads = (long long)N_NODES * 32;
    gcn_gather_kernel<<<(unsigned)((gthreads + 255) / 256), 256>>>(
        bias, alpha, out);
}